// round 1
// baseline (speedup 1.0000x reference)
#include <cuda_runtime.h>

#define NCOLS            696     // 16 + 120 + 560
#define NQ_TOTAL         174     // NCOLS / 4
#define ROWS_PER_BLOCK   128
#define THREADS          128
#define BUF_STRIDE       129     // 128 rows + 1 pad (conflict-free STS, 2-way LDS on writeout)

// Dubois t-norm for a,b >= 0:  a*b / max(max(a,b), lambda) == min(a, b, a*b/lambda)
__device__ __forceinline__ float tnorm(float a, float b, float inv_l) {
    return fminf(fminf(a, b), a * b * inv_l);
}

// Compute output columns [LO, HI) for this thread's row into transposed smem buf.
// Fully unrolled; `col` constant-folds, out-of-range columns are dead-code-eliminated.
template<int LO, int HI>
__device__ __forceinline__ void compute_chunk(const float xv[16], float inv_l,
                                              float* __restrict__ buf, int tid) {
    int col = 0;
    // singles: cols 0..15
    #pragma unroll
    for (int i = 0; i < 16; i++) {
        if (col >= LO && col < HI) buf[(col - LO) * BUF_STRIDE + tid] = xv[i];
        col++;
    }
    // pairs: cols 16..135, lexicographic (i<j)
    #pragma unroll
    for (int i = 0; i < 16; i++) {
        #pragma unroll
        for (int j = i + 1; j < 16; j++) {
            if (col >= LO && col < HI)
                buf[(col - LO) * BUF_STRIDE + tid] = tnorm(xv[i], xv[j], inv_l);
            col++;
        }
    }
    // triples: cols 136..695, lexicographic (i<j<k), fold order T(T(xi,xj), xk)
    #pragma unroll
    for (int i = 0; i < 16; i++) {
        #pragma unroll
        for (int j = i + 1; j < 16; j++) {
            float p = tnorm(xv[i], xv[j], inv_l);   // hoisted; dead if no k in range
            #pragma unroll
            for (int k = j + 1; k < 16; k++) {
                if (col >= LO && col < HI)
                    buf[(col - LO) * BUF_STRIDE + tid] = tnorm(p, xv[k], inv_l);
                col++;
            }
        }
    }
}

// Coalesced writeout of columns [LO, HI) for all 128 rows of this block.
template<int LO, int HI>
__device__ __forceinline__ void writeout_chunk(const float* __restrict__ buf,
                                               float4* __restrict__ out4,
                                               int row0, int tid) {
    constexpr int NQ = (HI - LO) / 4;   // float4s per row in this chunk
    #pragma unroll
    for (int it = 0; it < NQ; it++) {
        int idx = it * THREADS + tid;
        int q = idx % NQ;               // float4 index within chunk (fast-varying with tid)
        int r = idx / NQ;               // row within block
        float4 v;
        v.x = buf[(4 * q + 0) * BUF_STRIDE + r];
        v.y = buf[(4 * q + 1) * BUF_STRIDE + r];
        v.z = buf[(4 * q + 2) * BUF_STRIDE + r];
        v.w = buf[(4 * q + 3) * BUF_STRIDE + r];
        out4[(size_t)(row0 + r) * NQ_TOTAL + (LO / 4) + q] = v;
    }
}

__global__ void __launch_bounds__(THREADS)
dubois_kernel(const float* __restrict__ x,
              const float* __restrict__ lambda_,
              float* __restrict__ out) {
    __shared__ float buf[64 * BUF_STRIDE];   // 33,024 B

    const int tid  = threadIdx.x;
    const int row0 = blockIdx.x * ROWS_PER_BLOCK;
    const int row  = row0 + tid;

    const float inv_l = 1.0f / __ldg(lambda_);

    // Load this thread's 16 inputs into registers (4x LDG.128).
    float xv[16];
    const float4* xp = reinterpret_cast<const float4*>(x) + (size_t)row * 4;
    float4 a = xp[0], b = xp[1], c = xp[2], d = xp[3];
    xv[0]=a.x;  xv[1]=a.y;  xv[2]=a.z;  xv[3]=a.w;
    xv[4]=b.x;  xv[5]=b.y;  xv[6]=b.z;  xv[7]=b.w;
    xv[8]=c.x;  xv[9]=c.y;  xv[10]=c.z; xv[11]=c.w;
    xv[12]=d.x; xv[13]=d.y; xv[14]=d.z; xv[15]=d.w;

    float4* out4 = reinterpret_cast<float4*>(out);

#define DUBOIS_CHUNK(LO, HI)                            \
    compute_chunk<LO, HI>(xv, inv_l, buf, tid);         \
    __syncthreads();                                    \
    writeout_chunk<LO, HI>(buf, out4, row0, tid);       \
    __syncthreads();

    DUBOIS_CHUNK(0,   64)
    DUBOIS_CHUNK(64,  128)
    DUBOIS_CHUNK(128, 192)
    DUBOIS_CHUNK(192, 256)
    DUBOIS_CHUNK(256, 320)
    DUBOIS_CHUNK(320, 384)
    DUBOIS_CHUNK(384, 448)
    DUBOIS_CHUNK(448, 512)
    DUBOIS_CHUNK(512, 576)
    DUBOIS_CHUNK(576, 640)
    DUBOIS_CHUNK(640, 696)

#undef DUBOIS_CHUNK
}

extern "C" void kernel_launch(void* const* d_in, const int* in_sizes, int n_in,
                              void* d_out, int out_size) {
    const float* x   = (const float*)d_in[0];
    const float* lam = (const float*)d_in[1];
    float* out = (float*)d_out;

    int rows = in_sizes[0] / 16;                 // 131072
    int grid = rows / ROWS_PER_BLOCK;            // 1024
    dubois_kernel<<<grid, THREADS>>>(x, lam, out);
}